// round 3
// baseline (speedup 1.0000x reference)
#include <cuda_runtime.h>
#include <cuda_bf16.h>

// Problem constants (from reference): B=16384, CLIP=50, D=64,
// emb_user has NUM_FRIENDS+1 = 100001 rows, row NUM_FRIENDS is all-zero.
#define NUM_FRIENDS 100000
#define CLIP 50
#define DIM 64
#define WARPS_PER_BLOCK 8

__device__ __forceinline__ float fast_sigmoid(float x) {
    return 1.0f / (1.0f + __expf(-x));
}

__global__ __launch_bounds__(WARPS_PER_BLOCK * 32)
void gmf_kernel(const int* __restrict__ user_indices,
                const int* __restrict__ item_indices,
                const int* __restrict__ user_friend_indices,
                const float* __restrict__ emb_user,
                const float* __restrict__ emb_item,
                const float* __restrict__ affine_w,
                const float* __restrict__ affine_b,
                float* __restrict__ out,
                int B)
{
    const int w    = threadIdx.x >> 5;   // warp in block
    const int lane = threadIdx.x & 31;
    const int b    = blockIdx.x * WARPS_PER_BLOCK + w;   // sample id (warp-uniform)

    __shared__ int   s_fi[WARPS_PER_BLOCK][CLIP];
    __shared__ float s_gate[WARPS_PER_BLOCK][CLIP];

    if (b >= B) return;   // whole warp exits together (b is warp-uniform)

    const int u  = user_indices[b];
    const int it = item_indices[b];

    // Stage the 50 friend ids for this sample into shared (coalesced 200B read).
    const int* fptr = user_friend_indices + (size_t)u * CLIP;
    if (lane < CLIP)       s_fi[w][lane]       = __ldg(fptr + lane);
    if (lane + 32 < CLIP)  s_fi[w][lane + 32]  = __ldg(fptr + lane + 32);
    __syncwarp();

    // Each lane owns 2 dims: d = 2*lane, 2*lane+1.
    const float2 ie = *reinterpret_cast<const float2*>(emb_item + (size_t)it * DIM + 2 * lane);
    const float2 wv = *reinterpret_cast<const float2*>(affine_w + 2 * lane);
    const float  bb = __ldg(affine_b);
    const float2 wi = make_float2(ie.x * wv.x, ie.y * wv.y);

    float2 acc = make_float2(0.0f, 0.0f);
    int nreal = 0;

    // Depth-2 prefetch, 2 friends per iteration.
    int f0 = s_fi[w][0];
    int f1 = s_fi[w][1];
    float2 fe0 = *reinterpret_cast<const float2*>(emb_user + (size_t)f0 * DIM + 2 * lane);
    float2 fe1 = *reinterpret_cast<const float2*>(emb_user + (size_t)f1 * DIM + 2 * lane);

    #pragma unroll
    for (int c = 0; c < CLIP; c += 2) {
        int nf0 = 0, nf1 = 0;
        float2 fen0 = make_float2(0.0f, 0.0f);
        float2 fen1 = make_float2(0.0f, 0.0f);
        if (c + 2 < CLIP) {
            nf0 = s_fi[w][c + 2];
            nf1 = s_fi[w][c + 3];
            fen0 = *reinterpret_cast<const float2*>(emb_user + (size_t)nf0 * DIM + 2 * lane);
            fen1 = *reinterpret_cast<const float2*>(emb_user + (size_t)nf1 * DIM + 2 * lane);
        }

        nreal += (f0 != NUM_FRIENDS) + (f1 != NUM_FRIENDS);

        // Per-friend dot(fe, ie*w): butterfly reduce two friends in parallel (ILP).
        float s0 = fe0.x * wi.x + fe0.y * wi.y;
        float s1 = fe1.x * wi.x + fe1.y * wi.y;
        #pragma unroll
        for (int o = 16; o > 0; o >>= 1) {
            s0 += __shfl_xor_sync(0xffffffffu, s0, o);
            s1 += __shfl_xor_sync(0xffffffffu, s1, o);
        }

        // Padding friend rows are all-zero in emb_user, so s==0 and gate==sigmoid(bb),
        // matching the reference exactly; fe*gate contributes 0 to acc.
        const float g0 = fast_sigmoid(s0 + bb);
        const float g1 = fast_sigmoid(s1 + bb);

        acc.x += fe0.x * g0 + fe1.x * g1;
        acc.y += fe0.y * g0 + fe1.y * g1;

        if (lane == 0) {
            s_gate[w][c]     = g0;
            s_gate[w][c + 1] = g1;
        }

        f0 = nf0; f1 = nf1;
        fe0 = fen0; fe1 = fen1;
    }

    // rating = sigmoid( (sum_d acc[d]*ie[d]*w[d]) / nreal + bb )
    float part = acc.x * wi.x + acc.y * wi.y;
    #pragma unroll
    for (int o = 16; o > 0; o >>= 1)
        part += __shfl_xor_sync(0xffffffffu, part, o);

    if (lane == 0)
        out[b] = fast_sigmoid(part / (float)nreal + bb);

    // group_idx output: [B, CLIP] region after rating[B]. Coalesced 200B store.
    __syncwarp();
    float* gout = out + B + (size_t)b * CLIP;
    if (lane < CLIP)      gout[lane]      = s_gate[w][lane];
    if (lane + 32 < CLIP) gout[lane + 32] = s_gate[w][lane + 32];
}

extern "C" void kernel_launch(void* const* d_in, const int* in_sizes, int n_in,
                              void* d_out, int out_size) {
    const int*   user_indices        = (const int*)  d_in[0];
    const int*   item_indices        = (const int*)  d_in[1];
    const int*   user_friend_indices = (const int*)  d_in[2];
    const float* emb_user            = (const float*)d_in[3];
    const float* emb_item            = (const float*)d_in[4];
    const float* affine_w            = (const float*)d_in[5];
    const float* affine_b            = (const float*)d_in[6];
    float*       out                 = (float*)d_out;

    const int B = in_sizes[0];
    const int blocks = (B + WARPS_PER_BLOCK - 1) / WARPS_PER_BLOCK;
    gmf_kernel<<<blocks, WARPS_PER_BLOCK * 32>>>(
        user_indices, item_indices, user_friend_indices,
        emb_user, emb_item, affine_w, affine_b, out, B);
}

// round 4
// speedup vs baseline: 1.3395x; 1.3395x over previous
#include <cuda_runtime.h>
#include <cuda_bf16.h>

// B=16384, CLIP=50, D=64, emb_user has NUM_FRIENDS+1=100001 rows, row NUM_FRIENDS all-zero.
#define NUM_FRIENDS 100000
#define CLIP 50
#define DIM 64
#define WARPS_PER_BLOCK 8

__device__ __forceinline__ float fast_sigmoid(float x) {
    return 1.0f / (1.0f + __expf(-x));
}

// Layout: one warp per sample. Lanes 0-15 handle the EVEN friend of each pair,
// lanes 16-31 the ODD friend. Each lane owns 4 dims (float4): d = 4*(lane&15)..+3.
// Butterfly offsets 8,4,2,1 reduce the 64-dim dot within each 16-lane half,
// both friends concurrently in the same SHFL instructions.
__global__ __launch_bounds__(WARPS_PER_BLOCK * 32)
void gmf_kernel(const int* __restrict__ user_indices,
                const int* __restrict__ item_indices,
                const int* __restrict__ user_friend_indices,
                const float* __restrict__ emb_user,
                const float* __restrict__ emb_item,
                const float* __restrict__ affine_w,
                const float* __restrict__ affine_b,
                float* __restrict__ out,
                int B)
{
    const int w    = threadIdx.x >> 5;
    const int lane = threadIdx.x & 31;
    const int b    = blockIdx.x * WARPS_PER_BLOCK + w;   // warp-uniform

    __shared__ int   s_fi[WARPS_PER_BLOCK][CLIP];
    __shared__ float s_gate[WARPS_PER_BLOCK][CLIP];

    if (b >= B) return;

    const int u  = user_indices[b];
    const int it = item_indices[b];

    // Stage friend ids (coalesced 200B).
    const int* fptr = user_friend_indices + (size_t)u * CLIP;
    if (lane < CLIP)      s_fi[w][lane]      = __ldg(fptr + lane);
    if (lane + 32 < CLIP) s_fi[w][lane + 32] = __ldg(fptr + lane + 32);
    __syncwarp();

    const int half = lane >> 4;            // 0 = even friend, 1 = odd friend
    const int l4   = (lane & 15) << 2;     // this lane's dim base (0..60)

    const float4 ie = *reinterpret_cast<const float4*>(emb_item + (size_t)it * DIM + l4);
    const float4 wv = *reinterpret_cast<const float4*>(affine_w + l4);
    const float  bb = __ldg(affine_b);
    const float4 wi = make_float4(ie.x * wv.x, ie.y * wv.y, ie.z * wv.z, ie.w * wv.w);

    const float* __restrict__ eup = emb_user + l4;

    float4 acc = make_float4(0.f, 0.f, 0.f, 0.f);
    int nreal = 0;

    // Pipeline depth 2 (two friend-pairs in flight).
    int    f0  = s_fi[w][0 + half];
    int    f1  = s_fi[w][2 + half];
    float4 fe0 = *reinterpret_cast<const float4*>(eup + (size_t)f0 * DIM);
    float4 fe1 = *reinterpret_cast<const float4*>(eup + (size_t)f1 * DIM);

    #pragma unroll
    for (int c = 0; c < CLIP; c += 2) {
        int    fn  = NUM_FRIENDS;
        float4 fen = make_float4(0.f, 0.f, 0.f, 0.f);
        if (c + 4 < CLIP) {
            fn  = s_fi[w][c + 4 + half];
            fen = *reinterpret_cast<const float4*>(eup + (size_t)fn * DIM);
        }

        nreal += (f0 != NUM_FRIENDS);

        // dot(fe, ie*w) within this half (64 dims = 16 lanes x 4).
        float s = fe0.x * wi.x + fe0.y * wi.y + fe0.z * wi.z + fe0.w * wi.w;
        s += __shfl_xor_sync(0xffffffffu, s, 8);
        s += __shfl_xor_sync(0xffffffffu, s, 4);
        s += __shfl_xor_sync(0xffffffffu, s, 2);
        s += __shfl_xor_sync(0xffffffffu, s, 1);

        // Padding rows are all-zero -> s==0 -> gate==sigmoid(bb), matching reference.
        const float g = fast_sigmoid(s + bb);

        acc.x += fe0.x * g;
        acc.y += fe0.y * g;
        acc.z += fe0.z * g;
        acc.w += fe0.w * g;

        if ((lane & 15) == 0)            // lanes 0 and 16: one STS, two addresses
            s_gate[w][c + half] = g;

        f0 = f1;  fe0 = fe1;
        f1 = fn;  fe1 = fen;
    }

    // Combine halves: acc holds even-friend sums (lanes 0-15) / odd-friend sums (16-31),
    // each for its own 4 dims. Full 32-lane reduce of acc.wi covers all friends+dims.
    float part = acc.x * wi.x + acc.y * wi.y + acc.z * wi.z + acc.w * wi.w;
    #pragma unroll
    for (int o = 16; o > 0; o >>= 1)
        part += __shfl_xor_sync(0xffffffffu, part, o);

    // nreal: lanes in each half hold that half's count; one xor-16 gives the total.
    nreal += __shfl_xor_sync(0xffffffffu, nreal, 16);

    if (lane == 0)
        out[b] = fast_sigmoid(part / (float)nreal + bb);

    __syncwarp();
    float* gout = out + B + (size_t)b * CLIP;
    if (lane < CLIP)      gout[lane]      = s_gate[w][lane];
    if (lane + 32 < CLIP) gout[lane + 32] = s_gate[w][lane + 32];
}

extern "C" void kernel_launch(void* const* d_in, const int* in_sizes, int n_in,
                              void* d_out, int out_size) {
    const int*   user_indices        = (const int*)  d_in[0];
    const int*   item_indices        = (const int*)  d_in[1];
    const int*   user_friend_indices = (const int*)  d_in[2];
    const float* emb_user            = (const float*)d_in[3];
    const float* emb_item            = (const float*)d_in[4];
    const float* affine_w            = (const float*)d_in[5];
    const float* affine_b            = (const float*)d_in[6];
    float*       out                 = (float*)d_out;

    const int B = in_sizes[0];
    const int blocks = (B + WARPS_PER_BLOCK - 1) / WARPS_PER_BLOCK;
    gmf_kernel<<<blocks, WARPS_PER_BLOCK * 32>>>(
        user_indices, item_indices, user_friend_indices,
        emb_user, emb_item, affine_w, affine_b, out, B);
}

// round 5
// speedup vs baseline: 1.4381x; 1.0736x over previous
#include <cuda_runtime.h>
#include <cuda_bf16.h>

// B=16384, CLIP=50, D=64, emb_user has NUM_FRIENDS+1=100001 rows, row NUM_FRIENDS all-zero.
#define NUM_FRIENDS 100000
#define CLIP 50
#define CLIP_PAD 52          // 13 iterations x 4 friends
#define NITER 13
#define DIM 64
#define WARPS_PER_BLOCK 8

__device__ __forceinline__ float fast_sigmoid(float x) {
    return 1.0f / (1.0f + __expf(-x));
}

// One warp per sample. 4 friend-groups of 8 lanes each (group = lane>>3);
// each lane owns 8 dims (dl = (lane&7)*8, two float4s). A 64-dim dot reduces
// with 3 SHFLs (xor 4,2,1) inside the group; 4 friends are processed by every
// SHFL/MUFU instruction. Key identity: logit = sum_c s_c * sigmoid(s_c+b) / n + b,
// so no per-dim gated accumulator or final 64-dim reduce is needed.
__global__ __launch_bounds__(WARPS_PER_BLOCK * 32)
void gmf_kernel(const int* __restrict__ user_indices,
                const int* __restrict__ item_indices,
                const int* __restrict__ user_friend_indices,
                const float* __restrict__ emb_user,
                const float* __restrict__ emb_item,
                const float* __restrict__ affine_w,
                const float* __restrict__ affine_b,
                float* __restrict__ out,
                int B)
{
    const int w    = threadIdx.x >> 5;
    const int lane = threadIdx.x & 31;
    const int b    = blockIdx.x * WARPS_PER_BLOCK + w;   // warp-uniform

    __shared__ int   s_fi[WARPS_PER_BLOCK][CLIP_PAD];
    __shared__ float s_gate[WARPS_PER_BLOCK][CLIP_PAD];

    if (b >= B) return;

    const int u  = user_indices[b];
    const int it = item_indices[b];

    // Stage friend ids (coalesced 200B) + 2 sentinel pads.
    const int* fptr = user_friend_indices + (size_t)u * CLIP;
    if (lane < CLIP)        s_fi[w][lane]        = __ldg(fptr + lane);
    if (lane + 32 < CLIP)   s_fi[w][lane + 32]   = __ldg(fptr + lane + 32);
    if (lane < CLIP_PAD - CLIP) s_fi[w][CLIP + lane] = NUM_FRIENDS;
    __syncwarp();

    const int g  = lane >> 3;            // friend subgroup 0..3
    const int dl = (lane & 7) << 3;      // dim base 0..56 (8 dims per lane)

    const float4 ie0 = *reinterpret_cast<const float4*>(emb_item + (size_t)it * DIM + dl);
    const float4 ie1 = *reinterpret_cast<const float4*>(emb_item + (size_t)it * DIM + dl + 4);
    const float4 wv0 = *reinterpret_cast<const float4*>(affine_w + dl);
    const float4 wv1 = *reinterpret_cast<const float4*>(affine_w + dl + 4);
    const float  bb  = __ldg(affine_b);
    const float4 wiA = make_float4(ie0.x * wv0.x, ie0.y * wv0.y, ie0.z * wv0.z, ie0.w * wv0.w);
    const float4 wiB = make_float4(ie1.x * wv1.x, ie1.y * wv1.y, ie1.z * wv1.z, ie1.w * wv1.w);

    const float* __restrict__ eup = emb_user + dl;

    float sg    = 0.0f;   // sum of s_c * gate_c (uniform within group after reduce)
    int   nreal = 0;

    // Depth-2 rotating prefetch: iteration t consumes (a0,b0), t+1's data in (a1,b1),
    // t+2's loads issued at top of t.
    int f0 = s_fi[w][g];
    int f1 = s_fi[w][4 + g];
    float4 a0 = *reinterpret_cast<const float4*>(eup + (size_t)f0 * DIM);
    float4 b0 = *reinterpret_cast<const float4*>(eup + (size_t)f0 * DIM + 4);
    float4 a1 = *reinterpret_cast<const float4*>(eup + (size_t)f1 * DIM);
    float4 b1 = *reinterpret_cast<const float4*>(eup + (size_t)f1 * DIM + 4);

    #pragma unroll
    for (int t = 0; t < NITER; t++) {
        int fn = NUM_FRIENDS;
        float4 an = make_float4(0.f, 0.f, 0.f, 0.f);
        float4 bn = make_float4(0.f, 0.f, 0.f, 0.f);
        if (t + 2 < NITER) {
            fn = s_fi[w][(t + 2) * 4 + g];
            an = *reinterpret_cast<const float4*>(eup + (size_t)fn * DIM);
            bn = *reinterpret_cast<const float4*>(eup + (size_t)fn * DIM + 4);
        }

        nreal += (f0 != NUM_FRIENDS);

        // dot(fe, ie*w): two independent FFMA chains for ILP, then 3-SHFL reduce.
        float sA = a0.x * wiA.x + a0.y * wiA.y + a0.z * wiA.z + a0.w * wiA.w;
        float sB = b0.x * wiB.x + b0.y * wiB.y + b0.z * wiB.z + b0.w * wiB.w;
        float s  = sA + sB;
        s += __shfl_xor_sync(0xffffffffu, s, 4);
        s += __shfl_xor_sync(0xffffffffu, s, 2);
        s += __shfl_xor_sync(0xffffffffu, s, 1);

        // Padding rows are all-zero -> s==0 -> gate==sigmoid(bb) (reference-exact),
        // and s*gate contributes 0.
        const float gate = fast_sigmoid(s + bb);
        sg = fmaf(s, gate, sg);

        if ((lane & 7) == 0)
            s_gate[w][t * 4 + g] = gate;   // slots 50,51 written but never emitted

        f0 = f1; a0 = a1; b0 = b1;
        f1 = fn; a1 = an; b1 = bn;
    }

    // sg / nreal are uniform within each 8-lane group; combine the 4 groups.
    sg += __shfl_xor_sync(0xffffffffu, sg, 8);
    sg += __shfl_xor_sync(0xffffffffu, sg, 16);
    nreal += __shfl_xor_sync(0xffffffffu, nreal, 8);
    nreal += __shfl_xor_sync(0xffffffffu, nreal, 16);

    if (lane == 0)
        out[b] = fast_sigmoid(sg / (float)nreal + bb);

    __syncwarp();
    float* gout = out + B + (size_t)b * CLIP;
    if (lane < CLIP)      gout[lane]      = s_gate[w][lane];
    if (lane + 32 < CLIP) gout[lane + 32] = s_gate[w][lane + 32];
}

extern "C" void kernel_launch(void* const* d_in, const int* in_sizes, int n_in,
                              void* d_out, int out_size) {
    const int*   user_indices        = (const int*)  d_in[0];
    const int*   item_indices        = (const int*)  d_in[1];
    const int*   user_friend_indices = (const int*)  d_in[2];
    const float* emb_user            = (const float*)d_in[3];
    const float* emb_item            = (const float*)d_in[4];
    const float* affine_w            = (const float*)d_in[5];
    const float* affine_b            = (const float*)d_in[6];
    float*       out                 = (float*)d_out;

    const int B = in_sizes[0];
    const int blocks = (B + WARPS_PER_BLOCK - 1) / WARPS_PER_BLOCK;
    gmf_kernel<<<blocks, WARPS_PER_BLOCK * 32>>>(
        user_indices, item_indices, user_friend_indices,
        emb_user, emb_item, affine_w, affine_b, out, B);
}